// round 9
// baseline (speedup 1.0000x reference)
#include <cuda_runtime.h>
#include <cuda_fp16.h>
#include <cstdint>

namespace {

constexpr int SEQ = 2048, HD = 64, BQ = 64, BK = 64, NTH = 128;
constexpr int QT_N  = SEQ / BQ;          // 32 q tiles
constexpr int NBH   = 32;                // B*H
constexpr int ELEMS = NBH * SEQ * HD;    // 4,194,304

// K, V converted to fp16 (packed half2 words), [bh][s][d] order
__device__ uint32_t g_k16[ELEMS / 2];
__device__ uint32_t g_v16[ELEMS / 2];

// smem: 3-stage K ring (0,8K,16K) + 3-stage V ring (24K,32K,40K) = 48KB
constexpr uint32_t KRB = 0, VRB = 24576;
constexpr uint32_t SMEM_BYTES = 49152;   // 4 CTAs/SM (192KB of 228KB)

__device__ __forceinline__ uint32_t kslot(int j) { return KRB + (uint32_t)(j % 3) * 8192u; }
__device__ __forceinline__ uint32_t vslot(int j) { return VRB + (uint32_t)(j % 3) * 8192u; }

__device__ __forceinline__ uint32_t swz(uint32_t x) { return x ^ ((x >> 3) & 0x70u); }

__device__ __forceinline__ uint32_t s2u(const void* p) {
    uint32_t a;
    asm("{ .reg .u64 t; cvta.to.shared.u64 t, %1; cvt.u32.u64 %0, t; }" : "=r"(a) : "l"(p));
    return a;
}
__device__ __forceinline__ float ex2(float x) {
    float r;
    asm("ex2.approx.ftz.f32 %0, %1;" : "=f"(r) : "f"(x));
    return r;
}
__device__ __forceinline__ void ldsm4(uint32_t& r0, uint32_t& r1, uint32_t& r2, uint32_t& r3,
                                      uint32_t a) {
    asm volatile("ldmatrix.sync.aligned.m8n8.x4.shared.b16 {%0,%1,%2,%3}, [%4];"
                 : "=r"(r0), "=r"(r1), "=r"(r2), "=r"(r3) : "r"(a));
}
__device__ __forceinline__ void ldsm4t(uint32_t& r0, uint32_t& r1, uint32_t& r2, uint32_t& r3,
                                       uint32_t a) {
    asm volatile("ldmatrix.sync.aligned.m8n8.x4.trans.shared.b16 {%0,%1,%2,%3}, [%4];"
                 : "=r"(r0), "=r"(r1), "=r"(r2), "=r"(r3) : "r"(a));
}
__device__ __forceinline__ void mma_f16(float (&d)[4], const uint32_t* a,
                                        const uint32_t b0, const uint32_t b1) {
    asm volatile(
        "mma.sync.aligned.m16n8k16.row.col.f32.f16.f16.f32 "
        "{%0,%1,%2,%3}, {%4,%5,%6,%7}, {%8,%9}, {%0,%1,%2,%3};"
        : "+f"(d[0]), "+f"(d[1]), "+f"(d[2]), "+f"(d[3])
        : "r"(a[0]), "r"(a[1]), "r"(a[2]), "r"(a[3]), "r"(b0), "r"(b1));
}
__device__ __forceinline__ void cpa16(uint32_t dst, const void* src) {
    asm volatile("cp.async.cg.shared.global [%0], [%1], 16;" :: "r"(dst), "l"(src) : "memory");
}
#define CP_COMMIT asm volatile("cp.async.commit_group;" ::: "memory")
template <int N>
__device__ __forceinline__ void cp_wait() {
    asm volatile("cp.async.wait_group %0;" :: "n"(N) : "memory");
}

// ---------------- pre-pass: convert K,V to fp16 ----------------
__global__ __launch_bounds__(256)
void cvt_kv_kernel(const float4* __restrict__ K, const float4* __restrict__ V)
{
    int i = blockIdx.x * 256 + threadIdx.x;
    float4 k = K[i];
    __half2 a = __floats2half2_rn(k.x, k.y);
    __half2 b = __floats2half2_rn(k.z, k.w);
    g_k16[2*i]   = *reinterpret_cast<uint32_t*>(&a);
    g_k16[2*i+1] = *reinterpret_cast<uint32_t*>(&b);
    float4 v = V[i];
    a = __floats2half2_rn(v.x, v.y);
    b = __floats2half2_rn(v.z, v.w);
    g_v16[2*i]   = *reinterpret_cast<uint32_t*>(&a);
    g_v16[2*i+1] = *reinterpret_cast<uint32_t*>(&b);
}

// cp.async one 8KB tile (64 rows x 128B, swizzled)
__device__ __forceinline__ void issue_tile8k(uint32_t sdst, const uint32_t* garr,
                                             int bh, int kb, int tid)
{
    const char* src = (const char*)garr + (((size_t)bh * SEQ + (size_t)kb * BK) * HD) * 2;
    #pragma unroll
    for (int t = 0; t < 4; ++t) {
        uint32_t i  = (uint32_t)(t * NTH + tid);
        uint32_t off = (i >> 3) * 128u + (i & 7u) * 16u;
        cpa16(sdst + swz(off), src + off);
    }
}

// interleaved MMA block: S(next) = Q K^T from ssK and/or O += P V from ssV
template <bool DO_S, bool DO_PV>
__device__ __forceinline__ void mma_block(
    float (*s)[4], float (*o)[4],
    const uint32_t (*qf)[4], const uint32_t* p16,
    uint32_t ssK, uint32_t ssV,
    uint32_t nB, uint32_t kprtB, uint32_t rowV, uint32_t colV)
{
    #pragma unroll
    for (int ks = 0; ks < 4; ++ks) {
        #pragma unroll
        for (int p = 0; p < 4; ++p) {
            uint32_t k0, k1, k2, k3, v0, v1, v2, v3;
            if (DO_S) {
                uint32_t offB = (16u * p + nB) * 128u + kprtB + (uint32_t)ks * 32u;
                ldsm4(k0, k1, k2, k3, ssK + swz(offB));
            }
            if (DO_PV) {
                uint32_t offV = (16u * ks + rowV) * 128u + 32u * p + colV;
                ldsm4t(v0, v1, v2, v3, ssV + swz(offV));
            }
            if (DO_S) {
                mma_f16(s[2*p],   qf[ks], k0, k1);
                mma_f16(s[2*p+1], qf[ks], k2, k3);
            }
            if (DO_PV) {
                mma_f16(o[2*p],   p16 + 4*ks, v0, v1);
                mma_f16(o[2*p+1], p16 + 4*ks, v2, v3);
            }
        }
    }
}

__global__ __launch_bounds__(NTH, 4)
void fa_hmma_kernel(const float* __restrict__ Qg_, float* __restrict__ Og_)
{
    extern __shared__ __align__(1024) char smp[];
    const uint32_t sb = s2u(smp);

    const int tid  = threadIdx.x;
    const int lane = tid & 31, warp = tid >> 5;
    const int quad = lane >> 2, qp = lane & 3;
    const int qt = (QT_N - 1) - (int)blockIdx.x;   // heaviest first
    const int bh = blockIdx.y;

    const float* Qg = Qg_ + ((size_t)bh * SEQ + (size_t)qt * BQ) * HD;
    float*       Og = Og_ + ((size_t)bh * SEQ + (size_t)qt * BQ) * HD;

    const uint32_t rowA  = 16u * warp + (lane & 7) + 8u * ((lane >> 3) & 1);
    const uint32_t kprtA = ((uint32_t)lane >> 4) * 16u;
    const uint32_t nB    = 8u * ((uint32_t)lane >> 4) + (lane & 7);
    const uint32_t kprtB = ((lane >> 3) & 1) * 16u;
    const uint32_t rowV  = (uint32_t)(lane & 15);
    const uint32_t colV  = 16u * ((uint32_t)lane >> 4);

    // ---- stage Q (fp16, scale*log2e folded) into V slot 2; hoist A-frags ----
    constexpr float QSC = 0.125f * 1.44269504f;
    #pragma unroll
    for (int it = 0; it < 8; ++it) {
        int i = it * NTH + tid;
        int r = i >> 4, dg = i & 15;
        float4 v = reinterpret_cast<const float4*>(Qg)[i];
        __half2 a = __floats2half2_rn(v.x * QSC, v.y * QSC);
        __half2 b = __floats2half2_rn(v.z * QSC, v.w * QSC);
        uint32_t off = (uint32_t)r * 128u + (uint32_t)dg * 8u;
        *(uint32_t*)(smp + VRB + 16384 + swz(off))     = *reinterpret_cast<uint32_t*>(&a);
        *(uint32_t*)(smp + VRB + 16384 + swz(off + 4)) = *reinterpret_cast<uint32_t*>(&b);
    }
    __syncthreads();

    uint32_t qf[4][4];
    #pragma unroll
    for (int ks = 0; ks < 4; ++ks) {
        uint32_t offA = rowA * 128u + kprtA + (uint32_t)ks * 32u;
        ldsm4(qf[ks][0], qf[ks][1], qf[ks][2], qf[ks][3], sb + VRB + 16384u + swz(offA));
    }
    __syncthreads();   // V slot 2 free again (first overwritten by V(2) at iter 0)

    // ---- prime: gA = {K0,V0,K1}; gB = {V1,K2} ----
    issue_tile8k(sb + kslot(0), g_k16, bh, 0, tid);
    issue_tile8k(sb + vslot(0), g_v16, bh, 0, tid);
    if (qt >= 1) issue_tile8k(sb + kslot(1), g_k16, bh, 1, tid);
    CP_COMMIT;                           // gA
    if (qt >= 1) {
        issue_tile8k(sb + vslot(1), g_v16, bh, 1, tid);
        if (qt >= 2) issue_tile8k(sb + kslot(2), g_k16, bh, 2, tid);
        CP_COMMIT;                       // gB
        cp_wait<1>();                    // gA complete
    } else {
        cp_wait<0>();
    }
    __syncthreads();

    float o[8][4] = {};
    float m0 = -1e30f, m1 = -1e30f, l0 = 0.0f, l1 = 0.0f;
    const int qr0 = 16 * warp + quad, qr1 = qr0 + 8;

    // ---- S(0) ----
    float s[8][4] = {};
    mma_block<true, false>(s, o, qf, nullptr, sb + kslot(0), 0, nB, kprtB, rowV, colV);

    for (int kb = 0; kb <= qt; ++kb) {
        // ---- causal mask (diagonal tile only) ----
        if (kb == qt) {
            #pragma unroll
            for (int nt = 0; nt < 8; ++nt) {
                int c0 = 8 * nt + 2 * qp;
                if (c0 > qr0)     s[nt][0] = -1e30f;
                if (c0 + 1 > qr0) s[nt][1] = -1e30f;
                if (c0 > qr1)     s[nt][2] = -1e30f;
                if (c0 + 1 > qr1) s[nt][3] = -1e30f;
            }
        }

        // ---- online softmax (base-2 domain) -> P as fp16 ----
        float mt0 = -1e30f, mt1 = -1e30f;
        #pragma unroll
        for (int nt = 0; nt < 8; ++nt) {
            mt0 = fmaxf(mt0, fmaxf(s[nt][0], s[nt][1]));
            mt1 = fmaxf(mt1, fmaxf(s[nt][2], s[nt][3]));
        }
        mt0 = fmaxf(mt0, __shfl_xor_sync(~0u, mt0, 1));
        mt0 = fmaxf(mt0, __shfl_xor_sync(~0u, mt0, 2));
        mt1 = fmaxf(mt1, __shfl_xor_sync(~0u, mt1, 1));
        mt1 = fmaxf(mt1, __shfl_xor_sync(~0u, mt1, 2));
        float mn0 = fmaxf(m0, mt0), mn1 = fmaxf(m1, mt1);
        float c0 = ex2(m0 - mn0), c1 = ex2(m1 - mn1);
        m0 = mn0; m1 = mn1;

        uint32_t p16[16];
        float rs0 = 0.f, rs1 = 0.f;
        #pragma unroll
        for (int nt = 0; nt < 8; ++nt) {
            float e0 = ex2(s[nt][0] - mn0), e1 = ex2(s[nt][1] - mn0);
            float e2 = ex2(s[nt][2] - mn1), e3 = ex2(s[nt][3] - mn1);
            rs0 += e0 + e1; rs1 += e2 + e3;
            __half2 ha = __floats2half2_rn(e0, e1);
            __half2 hb = __floats2half2_rn(e2, e3);
            p16[2*nt]     = *reinterpret_cast<uint32_t*>(&ha);
            p16[2*nt + 1] = *reinterpret_cast<uint32_t*>(&hb);
        }
        rs0 += __shfl_xor_sync(~0u, rs0, 1); rs0 += __shfl_xor_sync(~0u, rs0, 2);
        rs1 += __shfl_xor_sync(~0u, rs1, 1); rs1 += __shfl_xor_sync(~0u, rs1, 2);
        l0 = l0 * c0 + rs0; l1 = l1 * c1 + rs1;

        // conditional O-rescale: c==1 exactly when the row max didn't change
        if (c0 < 1.0f || c1 < 1.0f) {
            #pragma unroll
            for (int nt = 0; nt < 8; ++nt) {
                o[nt][0] *= c0; o[nt][1] *= c0;
                o[nt][2] *= c1; o[nt][3] *= c1;
            }
        }

        // ---- single barrier + deep prefetch (2 tiles ahead) ----
        cp_wait<1>();      // group issued 2 iters ago (V(kb),K(kb+1)) complete
        __syncthreads();   // global visibility + all warps past prev mma reads
        if (kb + 2 <= qt) issue_tile8k(sb + vslot(kb + 2), g_v16, bh, kb + 2, tid);
        if (kb + 3 <= qt) issue_tile8k(sb + kslot(kb + 3), g_k16, bh, kb + 3, tid);
        CP_COMMIT;         // committed every iter (possibly empty) to keep indexing

        // ---- MMA: PV(kb) interleaved with S(kb+1); s reused in place ----
        const uint32_t ssV = sb + vslot(kb);
        if (kb < qt) {
            #pragma unroll
            for (int nt = 0; nt < 8; ++nt) {
                s[nt][0] = 0.f; s[nt][1] = 0.f; s[nt][2] = 0.f; s[nt][3] = 0.f;
            }
            mma_block<true, true>(s, o, qf, p16, sb + kslot(kb + 1), ssV,
                                  nB, kprtB, rowV, colV);
        } else {
            mma_block<false, true>(s, o, qf, p16, 0, ssV, nB, kprtB, rowV, colV);
        }
    }

    // ---- epilogue ----
    float rl0 = 1.0f / l0, rl1 = 1.0f / l1;
    #pragma unroll
    for (int nt = 0; nt < 8; ++nt) {
        int col = 8 * nt + 2 * qp;
        *reinterpret_cast<float2*>(Og + (size_t)qr0 * HD + col) =
            make_float2(o[nt][0] * rl0, o[nt][1] * rl0);
        *reinterpret_cast<float2*>(Og + (size_t)qr1 * HD + col) =
            make_float2(o[nt][2] * rl1, o[nt][3] * rl1);
    }
}

} // namespace

extern "C" void kernel_launch(void* const* d_in, const int* in_sizes, int n_in,
                              void* d_out, int out_size)
{
    const float* Q = (const float*)d_in[0];
    const float* K = (const float*)d_in[1];
    const float* V = (const float*)d_in[2];
    float*       O = (float*)d_out;

    cvt_kv_kernel<<<ELEMS / 4 / 256, 256>>>((const float4*)K, (const float4*)V);

    cudaFuncSetAttribute(fa_hmma_kernel,
                         cudaFuncAttributeMaxDynamicSharedMemorySize, SMEM_BYTES);
    dim3 grid(QT_N, NBH);
    fa_hmma_kernel<<<grid, NTH, SMEM_BYTES>>>(Q, O);
}

// round 10
// speedup vs baseline: 1.1274x; 1.1274x over previous
#include <cuda_runtime.h>
#include <cuda_fp16.h>
#include <cstdint>

namespace {

constexpr int SEQ = 2048, HD = 64, BQ = 64, BK = 64, NTH = 128;
constexpr int QT_N  = SEQ / BQ;          // 32 q tiles
constexpr int NBH   = 32;                // B*H
constexpr int ELEMS = NBH * SEQ * HD;    // 4,194,304

// K, V converted to fp16 (packed half2 words), [bh][s][d] order
__device__ uint32_t g_k16[ELEMS / 2];
__device__ uint32_t g_v16[ELEMS / 2];

// smem: K ring 2x8KB, V ring 2x8KB. Q staged in VST1 pre-loop.  (R7 layout)
constexpr uint32_t KST0 = 0, KST1 = 8192, VST0 = 16384, VST1 = 24576;
constexpr uint32_t SMEM_BYTES = 32768;   // 4 CTAs/SM

__device__ __forceinline__ uint32_t swz(uint32_t x) { return x ^ ((x >> 3) & 0x70u); }

__device__ __forceinline__ uint32_t s2u(const void* p) {
    uint32_t a;
    asm("{ .reg .u64 t; cvta.to.shared.u64 t, %1; cvt.u32.u64 %0, t; }" : "=r"(a) : "l"(p));
    return a;
}
__device__ __forceinline__ float ex2(float x) {
    float r;
    asm("ex2.approx.ftz.f32 %0, %1;" : "=f"(r) : "f"(x));
    return r;
}
// two exp2's at once on the MUFU pipe; input/out packed half2
__device__ __forceinline__ uint32_t ex2_h2(uint32_t x) {
    uint32_t r;
    asm("ex2.approx.f16x2 %0, %1;" : "=r"(r) : "r"(x));
    return r;
}
__device__ __forceinline__ void ldsm4(uint32_t& r0, uint32_t& r1, uint32_t& r2, uint32_t& r3,
                                      uint32_t a) {
    asm volatile("ldmatrix.sync.aligned.m8n8.x4.shared.b16 {%0,%1,%2,%3}, [%4];"
                 : "=r"(r0), "=r"(r1), "=r"(r2), "=r"(r3) : "r"(a));
}
__device__ __forceinline__ void ldsm4t(uint32_t& r0, uint32_t& r1, uint32_t& r2, uint32_t& r3,
                                       uint32_t a) {
    asm volatile("ldmatrix.sync.aligned.m8n8.x4.trans.shared.b16 {%0,%1,%2,%3}, [%4];"
                 : "=r"(r0), "=r"(r1), "=r"(r2), "=r"(r3) : "r"(a));
}
__device__ __forceinline__ void mma_f16(float (&d)[4], const uint32_t* a,
                                        const uint32_t b0, const uint32_t b1) {
    asm volatile(
        "mma.sync.aligned.m16n8k16.row.col.f32.f16.f16.f32 "
        "{%0,%1,%2,%3}, {%4,%5,%6,%7}, {%8,%9}, {%0,%1,%2,%3};"
        : "+f"(d[0]), "+f"(d[1]), "+f"(d[2]), "+f"(d[3])
        : "r"(a[0]), "r"(a[1]), "r"(a[2]), "r"(a[3]), "r"(b0), "r"(b1));
}
__device__ __forceinline__ void cpa16(uint32_t dst, const void* src) {
    asm volatile("cp.async.cg.shared.global [%0], [%1], 16;" :: "r"(dst), "l"(src) : "memory");
}
#define CP_COMMIT asm volatile("cp.async.commit_group;" ::: "memory")
template <int N>
__device__ __forceinline__ void cp_wait() {
    asm volatile("cp.async.wait_group %0;" :: "n"(N) : "memory");
}

// ---------------- pre-pass: convert K,V to fp16 ----------------
__global__ __launch_bounds__(256)
void cvt_kv_kernel(const float4* __restrict__ K, const float4* __restrict__ V)
{
    int i = blockIdx.x * 256 + threadIdx.x;
    float4 k = K[i];
    __half2 a = __floats2half2_rn(k.x, k.y);
    __half2 b = __floats2half2_rn(k.z, k.w);
    g_k16[2*i]   = *reinterpret_cast<uint32_t*>(&a);
    g_k16[2*i+1] = *reinterpret_cast<uint32_t*>(&b);
    float4 v = V[i];
    a = __floats2half2_rn(v.x, v.y);
    b = __floats2half2_rn(v.z, v.w);
    g_v16[2*i]   = *reinterpret_cast<uint32_t*>(&a);
    g_v16[2*i+1] = *reinterpret_cast<uint32_t*>(&b);
}

// cp.async one 8KB tile (64 rows x 128B, swizzled)
__device__ __forceinline__ void issue_tile8k(uint32_t sdst, const uint32_t* garr,
                                             int bh, int kb, int tid)
{
    const char* src = (const char*)garr + (((size_t)bh * SEQ + (size_t)kb * BK) * HD) * 2;
    #pragma unroll
    for (int t = 0; t < 4; ++t) {
        uint32_t i  = (uint32_t)(t * NTH + tid);
        uint32_t off = (i >> 3) * 128u + (i & 7u) * 16u;
        cpa16(sdst + swz(off), src + off);
    }
}

// interleaved MMA block: S(next) = Q K^T from ssK and/or {O,l} += P [V|1] from ssV
template <bool DO_S, bool DO_PV>
__device__ __forceinline__ void mma_block(
    float (*s)[4], float (*o)[4], float (&ol)[4],
    const uint32_t (*qf)[4], const uint32_t* p16, uint32_t bone,
    uint32_t ssK, uint32_t ssV,
    uint32_t nB, uint32_t kprtB, uint32_t rowV, uint32_t colV)
{
    #pragma unroll
    for (int ks = 0; ks < 4; ++ks) {
        if (DO_PV)   // ones-column: row-sum of P accumulates on the tensor pipe
            mma_f16(ol, p16 + 4*ks, bone, bone);
        #pragma unroll
        for (int p = 0; p < 4; ++p) {
            uint32_t k0, k1, k2, k3, v0, v1, v2, v3;
            if (DO_S) {
                uint32_t offB = (16u * p + nB) * 128u + kprtB + (uint32_t)ks * 32u;
                ldsm4(k0, k1, k2, k3, ssK + swz(offB));
            }
            if (DO_PV) {
                uint32_t offV = (16u * ks + rowV) * 128u + 32u * p + colV;
                ldsm4t(v0, v1, v2, v3, ssV + swz(offV));
            }
            if (DO_S) {
                mma_f16(s[2*p],   qf[ks], k0, k1);
                mma_f16(s[2*p+1], qf[ks], k2, k3);
            }
            if (DO_PV) {
                mma_f16(o[2*p],   p16 + 4*ks, v0, v1);
                mma_f16(o[2*p+1], p16 + 4*ks, v2, v3);
            }
        }
    }
}

__global__ __launch_bounds__(NTH, 4)
void fa_hmma_kernel(const float* __restrict__ Qg_, float* __restrict__ Og_)
{
    extern __shared__ __align__(1024) char smp[];
    const uint32_t sb = s2u(smp);

    const int tid  = threadIdx.x;
    const int lane = tid & 31, warp = tid >> 5;
    const int quad = lane >> 2, qp = lane & 3;
    const int qt = (QT_N - 1) - (int)blockIdx.x;   // heaviest first
    const int bh = blockIdx.y;

    const float* Qg = Qg_ + ((size_t)bh * SEQ + (size_t)qt * BQ) * HD;
    float*       Og = Og_ + ((size_t)bh * SEQ + (size_t)qt * BQ) * HD;

    const uint32_t rowA  = 16u * warp + (lane & 7) + 8u * ((lane >> 3) & 1);
    const uint32_t kprtA = ((uint32_t)lane >> 4) * 16u;
    const uint32_t nB    = 8u * ((uint32_t)lane >> 4) + (lane & 7);
    const uint32_t kprtB = ((lane >> 3) & 1) * 16u;
    const uint32_t rowV  = (uint32_t)(lane & 15);
    const uint32_t colV  = 16u * ((uint32_t)lane >> 4);
    // B fragment of the ones-column (n=0): lanes 0..3 hold {1,1},{1,1}
    const uint32_t bone  = (lane < 4) ? 0x3C003C00u : 0u;

    // ---- stage Q (fp16, scale*log2e folded) into VST1, hoist A-fragments ----
    constexpr float QSC = 0.125f * 1.44269504f;
    #pragma unroll
    for (int it = 0; it < 8; ++it) {
        int i = it * NTH + tid;
        int r = i >> 4, dg = i & 15;
        float4 v = reinterpret_cast<const float4*>(Qg)[i];
        __half2 a = __floats2half2_rn(v.x * QSC, v.y * QSC);
        __half2 b = __floats2half2_rn(v.z * QSC, v.w * QSC);
        uint32_t off = (uint32_t)r * 128u + (uint32_t)dg * 8u;
        *(uint32_t*)(smp + VST1 + swz(off))     = *reinterpret_cast<uint32_t*>(&a);
        *(uint32_t*)(smp + VST1 + swz(off + 4)) = *reinterpret_cast<uint32_t*>(&b);
    }
    __syncthreads();

    uint32_t qf[4][4];
    #pragma unroll
    for (int ks = 0; ks < 4; ++ks) {
        uint32_t offA = rowA * 128u + kprtA + (uint32_t)ks * 32u;
        ldsm4(qf[ks][0], qf[ks][1], qf[ks][2], qf[ks][3], sb + VST1 + swz(offA));
    }
    __syncthreads();   // VST1 free again

    // ---- prime: K0,V0 (g0); K1 (g1, may be absent) ----
    issue_tile8k(sb + KST0, g_k16, bh, 0, tid);
    issue_tile8k(sb + VST0, g_v16, bh, 0, tid);
    CP_COMMIT;
    if (qt >= 1) {
        issue_tile8k(sb + KST1, g_k16, bh, 1, tid);
        CP_COMMIT;
        cp_wait<1>();      // K0,V0 ready
    } else {
        CP_COMMIT;
        cp_wait<0>();
    }
    __syncthreads();

    float o[8][4] = {};
    float ol[4] = {};                       // [O | l] augmented accumulator
    float m0 = -1e30f, m1 = -1e30f;
    const int qr0 = 16 * warp + quad, qr1 = qr0 + 8;

    // ---- S(0) ----
    float s[8][4] = {};
    mma_block<true, false>(s, o, ol, qf, nullptr, bone,
                           sb + KST0, 0, nB, kprtB, rowV, colV);

    for (int kb = 0; kb <= qt; ++kb) {
        // ---- causal mask (diagonal tile only) ----
        if (kb == qt) {
            #pragma unroll
            for (int nt = 0; nt < 8; ++nt) {
                int c0 = 8 * nt + 2 * qp;
                if (c0 > qr0)     s[nt][0] = -1e30f;
                if (c0 + 1 > qr0) s[nt][1] = -1e30f;
                if (c0 > qr1)     s[nt][2] = -1e30f;
                if (c0 + 1 > qr1) s[nt][3] = -1e30f;
            }
        }

        // ---- online softmax (base-2 domain) -> P as fp16 via ex2.f16x2 ----
        float mt0 = -1e30f, mt1 = -1e30f;
        #pragma unroll
        for (int nt = 0; nt < 8; ++nt) {
            mt0 = fmaxf(mt0, fmaxf(s[nt][0], s[nt][1]));
            mt1 = fmaxf(mt1, fmaxf(s[nt][2], s[nt][3]));
        }
        mt0 = fmaxf(mt0, __shfl_xor_sync(~0u, mt0, 1));
        mt0 = fmaxf(mt0, __shfl_xor_sync(~0u, mt0, 2));
        mt1 = fmaxf(mt1, __shfl_xor_sync(~0u, mt1, 1));
        mt1 = fmaxf(mt1, __shfl_xor_sync(~0u, mt1, 2));
        float mn0 = fmaxf(m0, mt0), mn1 = fmaxf(m1, mt1);
        float c0 = ex2(m0 - mn0), c1 = ex2(m1 - mn1);
        m0 = mn0; m1 = mn1;

        uint32_t p16[16];
        #pragma unroll
        for (int nt = 0; nt < 8; ++nt) {
            __half2 da = __floats2half2_rn(s[nt][0] - mn0, s[nt][1] - mn0);
            __half2 db = __floats2half2_rn(s[nt][2] - mn1, s[nt][3] - mn1);
            p16[2*nt]     = ex2_h2(*reinterpret_cast<uint32_t*>(&da));
            p16[2*nt + 1] = ex2_h2(*reinterpret_cast<uint32_t*>(&db));
        }

        // rescale O and l-accumulator by corr (l follows the same recurrence)
        #pragma unroll
        for (int nt = 0; nt < 8; ++nt) {
            o[nt][0] *= c0; o[nt][1] *= c0;
            o[nt][2] *= c1; o[nt][3] *= c1;
        }
        ol[0] *= c0; ol[1] *= c0; ol[2] *= c1; ol[3] *= c1;

        // ---- prefetch rotation (R7 rhythm) ----
        __syncthreads();   // all warps done reading K(kb) [S] & V(kb-1) [PV]
        if (kb < qt) {
            issue_tile8k(sb + (((kb + 1) & 1) ? VST1 : VST0), g_v16, bh, kb + 1, tid);
            if (kb + 2 <= qt)
                issue_tile8k(sb + ((kb & 1) ? KST1 : KST0), g_k16, bh, kb + 2, tid);
            CP_COMMIT;
            cp_wait<1>();  // K(kb+1), V(kb) ready
        } else {
            cp_wait<0>();  // V(qt) ready
        }
        __syncthreads();

        // ---- MMA: PV(kb)+Σp interleaved with S(kb+1); s reused in place ----
        const uint32_t ssV = sb + ((kb & 1) ? VST1 : VST0);
        if (kb < qt) {
            #pragma unroll
            for (int nt = 0; nt < 8; ++nt) {
                s[nt][0] = 0.f; s[nt][1] = 0.f; s[nt][2] = 0.f; s[nt][3] = 0.f;
            }
            const uint32_t ssK = sb + (((kb + 1) & 1) ? KST1 : KST0);
            mma_block<true, true>(s, o, ol, qf, p16, bone,
                                  ssK, ssV, nB, kprtB, rowV, colV);
        } else {
            mma_block<false, true>(s, o, ol, qf, p16, bone,
                                   0, ssV, nB, kprtB, rowV, colV);
        }
    }

    // ---- epilogue: l lives in col 0 (qp==0 lanes); broadcast within quad ----
    float l0 = __shfl_sync(0xffffffffu, ol[0], lane & ~3);
    float l1 = __shfl_sync(0xffffffffu, ol[2], lane & ~3);
    float rl0 = 1.0f / l0, rl1 = 1.0f / l1;
    #pragma unroll
    for (int nt = 0; nt < 8; ++nt) {
        int col = 8 * nt + 2 * qp;
        *reinterpret_cast<float2*>(Og + (size_t)qr0 * HD + col) =
            make_float2(o[nt][0] * rl0, o[nt][1] * rl0);
        *reinterpret_cast<float2*>(Og + (size_t)qr1 * HD + col) =
            make_float2(o[nt][2] * rl1, o[nt][3] * rl1);
    }
}

} // namespace

extern "C" void kernel_launch(void* const* d_in, const int* in_sizes, int n_in,
                              void* d_out, int out_size)
{
    const float* Q = (const float*)d_in[0];
    const float* K = (const float*)d_in[1];
    const float* V = (const float*)d_in[2];
    float*       O = (float*)d_out;

    cvt_kv_kernel<<<ELEMS / 4 / 256, 256>>>((const float4*)K, (const float4*)V);

    cudaFuncSetAttribute(fa_hmma_kernel,
                         cudaFuncAttributeMaxDynamicSharedMemorySize, SMEM_BYTES);
    dim3 grid(QT_N, NBH);
    fa_hmma_kernel<<<grid, NTH, SMEM_BYTES>>>(Q, O);
}